// round 7
// baseline (speedup 1.0000x reference)
#include <cuda_runtime.h>
#include <cuda_bf16.h>
#include <cstdint>

// HilbertSchmidtVQ forward: out == rho_flat bitwise (q - stop_grad(q) == 0),
// so the roofline-optimal kernel is a streaming copy.
//
// R7: split-residency partition. Input (64 MB) + output (64 MB) together are
// ~= L2 capacity (~126 MB). Keep 92% of BOTH arrays L2-resident across graph
// replays (default policy: loads hit, stores re-dirty in place, no writeback
// in steady state); the remaining 8% (CTAs >= SPLIT) streams through DRAM
// with evict-first (.cs) on both load and store so it never displaces the
// resident set. DRAM traffic/replay: ~78 MB -> ~15 MB.
// Discriminates DRAM-bound vs LTS-cap-bound: if DRAM was binding, dur drops
// to the LTS floor (~13-14 us); if flat, 18.3 us is the chip floor.

#define UNROLL 8
#define THREADS 256
#define SPLIT 1884   // CTAs [0,1884): resident policy; [1884,2048): streaming

__global__ __launch_bounds__(THREADS) void vq_forward_copy_kernel(
    const float4* __restrict__ src, float4* __restrict__ dst)
{
    const size_t base = (size_t)blockIdx.x * (THREADS * UNROLL) + threadIdx.x;
    const float4* s = src + base;
    float4*       d = dst + base;

    float4 v[UNROLL];

    if (blockIdx.x < SPLIT) {
        // Resident partition: default policy both ways. These lines live in
        // L2 across replays — loads hit, stores re-dirty without writeback.
#pragma unroll
        for (int k = 0; k < UNROLL; ++k) {
            v[k] = s[k * THREADS];
        }
#pragma unroll
        for (int k = 0; k < UNROLL; ++k) {
            d[k * THREADS] = v[k];
        }
    } else {
        // Streaming partition: evict-first both ways; must not displace the
        // resident set. ~10.5 MB of DRAM traffic per replay.
#pragma unroll
        for (int k = 0; k < UNROLL; ++k) {
            asm volatile("ld.global.cs.v4.f32 {%0, %1, %2, %3}, [%4];"
                         : "=f"(v[k].x), "=f"(v[k].y), "=f"(v[k].z), "=f"(v[k].w)
                         : "l"(s + k * THREADS));
        }
#pragma unroll
        for (int k = 0; k < UNROLL; ++k) {
            asm volatile("st.global.cs.v4.f32 [%0], {%1, %2, %3, %4};"
                         :: "l"(d + k * THREADS),
                            "f"(v[k].x), "f"(v[k].y), "f"(v[k].z), "f"(v[k].w)
                         : "memory");
        }
    }
}

extern "C" void kernel_launch(void* const* d_in, const int* in_sizes, int n_in,
                              void* d_out, int out_size) {
    const float4* src = (const float4*)d_in[0];
    float4* dst = (float4*)d_out;

    const int n_vec = out_size / 4;           // 4,194,304 float4
    const int per_cta = THREADS * UNROLL;     // 2048 float4 per CTA
    const int blocks = n_vec / per_cta;       // exactly 2048 CTAs
    vq_forward_copy_kernel<<<blocks, THREADS>>>(src, dst);
}

// round 8
// speedup vs baseline: 1.2117x; 1.2117x over previous
#include <cuda_runtime.h>
#include <cuda_bf16.h>
#include <cstdint>

// HilbertSchmidtVQ forward: out == rho_flat bitwise (q - stop_grad(q) == 0),
// so the roofline-optimal kernel is a streaming copy.
//
// FINAL (R8 = R5, the measured optimum): this copy is bound by the B300 LTS
// throughput cap (~6300 B/cyc, path-independent). LTS traffic is fixed at
// 128 MB (64 MB load + 64 MB store requests), giving a hard floor of
// ~18.3 us; R2/R5/R6 all sit exactly on it (7.0 TB/s LTS) despite wildly
// different occupancy/MLP/cache-policy — confirmed floor.
//   - 8x front-batched LDG.128 (MLP=8), no bounds predicates
//     (4,194,304 float4 = 2048 CTAs x 256 thr x 8 exactly), regs=32, occ ~80%
//   - st.global.cs evict-first stores (keeps the input L2-resident across
//     graph replays; minimizes DRAM-side pressure under the LTS cap)

#define UNROLL 8
#define THREADS 256

__global__ __launch_bounds__(THREADS) void vq_forward_copy_kernel(
    const float4* __restrict__ src, float4* __restrict__ dst)
{
    const size_t base = (size_t)blockIdx.x * (THREADS * UNROLL) + threadIdx.x;
    const float4* s = src + base;
    float4*       d = dst + base;

    float4 v[UNROLL];

    // Front-batched independent 128-bit loads (MLP=8).
#pragma unroll
    for (int k = 0; k < UNROLL; ++k) {
        v[k] = s[k * THREADS];
    }

    // Evict-first stores: write stream leaves L2 quickly, input stays resident.
#pragma unroll
    for (int k = 0; k < UNROLL; ++k) {
        asm volatile("st.global.cs.v4.f32 [%0], {%1, %2, %3, %4};"
                     :: "l"(d + k * THREADS),
                        "f"(v[k].x), "f"(v[k].y), "f"(v[k].z), "f"(v[k].w)
                     : "memory");
    }
}

extern "C" void kernel_launch(void* const* d_in, const int* in_sizes, int n_in,
                              void* d_out, int out_size) {
    const float4* src = (const float4*)d_in[0];
    float4* dst = (float4*)d_out;

    const int n_vec = out_size / 4;           // 4,194,304 float4
    const int per_cta = THREADS * UNROLL;     // 2048 float4 per CTA
    const int blocks = n_vec / per_cta;       // exactly 2048 CTAs
    vq_forward_copy_kernel<<<blocks, THREADS>>>(src, dst);
}

// round 9
// speedup vs baseline: 1.2301x; 1.0152x over previous
#include <cuda_runtime.h>
#include <cuda_bf16.h>
#include <cstdint>

// HilbertSchmidtVQ forward: out == rho_flat bitwise, since
// quantized - stop_gradient(quantized) == 0 exactly (same array subtracted
// from itself; stop_gradient is a value-identity). The distance matrix,
// argmin, and gather affect gradients only. The forward kernel is therefore
// a pure 64 MB device-to-device copy.
//
// FINAL: the copy is bound by the B300 chip-level LTS throughput cap
// (~6300 B/cyc, path-independent — LDG, LDG.256, and TMA all hit it).
// LTS traffic is irreducibly 128 MB (64 MB load + 64 MB store requests),
// giving a hard floor of ~18.3 us; measured 18.2-18.6 us across every
// occupancy / MLP / load-width / L2-policy variant (R2-R8), i.e. the kernel
// sits exactly on the hardware roofline at ~7.0 TB/s of L2 throughput.
//
// Configuration (measured optimum):
//  - 8x front-batched independent LDG.128 per thread (MLP=8)
//  - no bounds predicates: 4,194,304 float4 = 2048 CTAs x 256 thr x 8 exact
//  - regs=32, occ ~80%
//  - st.global.cs evict-first stores: the write stream leaves L2 quickly so
//    the input stays L2-resident across graph replays (DRAM traffic ~= the
//    write stream only), minimizing DRAM-side pressure under the LTS cap.

#define UNROLL 8
#define THREADS 256

__global__ __launch_bounds__(THREADS) void vq_forward_copy_kernel(
    const float4* __restrict__ src, float4* __restrict__ dst)
{
    const size_t base = (size_t)blockIdx.x * (THREADS * UNROLL) + threadIdx.x;
    const float4* s = src + base;
    float4*       d = dst + base;

    float4 v[UNROLL];

    // Front-batched independent 128-bit loads (MLP=8).
#pragma unroll
    for (int k = 0; k < UNROLL; ++k) {
        v[k] = s[k * THREADS];
    }

    // Evict-first stores: write stream leaves L2 quickly, input stays resident.
#pragma unroll
    for (int k = 0; k < UNROLL; ++k) {
        asm volatile("st.global.cs.v4.f32 [%0], {%1, %2, %3, %4};"
                     :: "l"(d + k * THREADS),
                        "f"(v[k].x), "f"(v[k].y), "f"(v[k].z), "f"(v[k].w)
                     : "memory");
    }
}

extern "C" void kernel_launch(void* const* d_in, const int* in_sizes, int n_in,
                              void* d_out, int out_size) {
    const float4* src = (const float4*)d_in[0];
    float4* dst = (float4*)d_out;

    const int n_vec = out_size / 4;           // 4,194,304 float4
    const int per_cta = THREADS * UNROLL;     // 2048 float4 per CTA
    const int blocks = n_vec / per_cta;       // exactly 2048 CTAs
    vq_forward_copy_kernel<<<blocks, THREADS>>>(src, dst);
}